// round 1
// baseline (speedup 1.0000x reference)
#include <cuda_runtime.h>
#include <cuda_bf16.h>
#include <math_constants.h>

// ---------------------------------------------------------------------------
// SingleAttentionHead: x[8,2048,1024] f32, Wq/Wk/Wv[64,1024] f32
// out[8,2048,64] f32 = causal-softmax( (xWq^T)(xWk^T)^T / 8 ) @ (xWv^T)
// ---------------------------------------------------------------------------

#define B_   8
#define T_   2048
#define C_   1024
#define H_   64
#define ROWS (B_ * T_)          // 16384

// scratch for q,k,v  (device globals: allocation-free rule)
__device__ float g_q[ROWS * H_];
__device__ float g_k[ROWS * H_];
__device__ float g_v[ROWS * H_];

// ===========================================================================
// Kernel 1: fused QKV projection.
// C[16384,192] = X[16384,1024] * W^T   where W rows 0..63=Wq, 64..127=Wk, 128..191=Wv
// Tiling: BM=64, BN=192, BK=32, 256 threads, per-thread micro-tile 4x12.
// ===========================================================================
#define K1_BM 64
#define K1_BN 192
#define K1_BK 32
#define K1_WS_STRIDE 196   // padded (multiple of 4 for float4 reads)
#define K1_XS_STRIDE 33

__global__ __launch_bounds__(256)
void qkv_proj_kernel(const float* __restrict__ x,
                     const float* __restrict__ Wq,
                     const float* __restrict__ Wk,
                     const float* __restrict__ Wv)
{
    __shared__ float Xs[K1_BM * K1_XS_STRIDE];       // 64 x 32 (+pad)
    __shared__ float Ws[K1_BK * K1_WS_STRIDE];       // 32 x 192 (+pad)

    const int tid  = threadIdx.x;
    const int row0 = blockIdx.x * K1_BM;

    const int tr = tid >> 4;          // 0..15  -> rows tr*4 .. tr*4+3
    const int tc = tid & 15;          // 0..15  -> cols tc*12 .. tc*12+11

    float acc[4][12];
#pragma unroll
    for (int i = 0; i < 4; i++)
#pragma unroll
        for (int j = 0; j < 12; j++) acc[i][j] = 0.0f;

    // tile-load index helpers
    const int lx_c  = tid & 31;       // X: column within BK
    const int lx_r0 = tid >> 5;       // X: row group (8 rows apart)
    const int lw_k  = tid & 31;       // W: k within BK (coalesced over k)
    const int lw_n0 = tid >> 5;       // W: base col group

    for (int kt = 0; kt < C_ / K1_BK; kt++) {
        const int k0 = kt * K1_BK;

        // load X tile (64x32)
#pragma unroll
        for (int ii = 0; ii < 8; ii++) {
            int r = lx_r0 + ii * 8;
            Xs[r * K1_XS_STRIDE + lx_c] = x[(row0 + r) * C_ + k0 + lx_c];
        }
        // load W tile (32 x 192), coalesced along k per warp
#pragma unroll
        for (int jj = 0; jj < 24; jj++) {
            int n = lw_n0 + jj * 8;
            const float* wsrc;
            if (n < 64)       wsrc = Wq + n * C_;
            else if (n < 128) wsrc = Wk + (n - 64) * C_;
            else              wsrc = Wv + (n - 128) * C_;
            Ws[lw_k * K1_WS_STRIDE + n] = wsrc[k0 + lw_k];
        }
        __syncthreads();

#pragma unroll 4
        for (int k = 0; k < K1_BK; k++) {
            float a[4];
#pragma unroll
            for (int i = 0; i < 4; i++)
                a[i] = Xs[(tr * 4 + i) * K1_XS_STRIDE + k];
            const float4* wr = (const float4*)(Ws + k * K1_WS_STRIDE + tc * 12);
            float4 b0 = wr[0], b1 = wr[1], b2 = wr[2];
#pragma unroll
            for (int i = 0; i < 4; i++) {
                acc[i][0]  += a[i] * b0.x;  acc[i][1]  += a[i] * b0.y;
                acc[i][2]  += a[i] * b0.z;  acc[i][3]  += a[i] * b0.w;
                acc[i][4]  += a[i] * b1.x;  acc[i][5]  += a[i] * b1.y;
                acc[i][6]  += a[i] * b1.z;  acc[i][7]  += a[i] * b1.w;
                acc[i][8]  += a[i] * b2.x;  acc[i][9]  += a[i] * b2.y;
                acc[i][10] += a[i] * b2.z;  acc[i][11] += a[i] * b2.w;
            }
        }
        __syncthreads();
    }

    // epilogue: scatter to g_q / g_k / g_v
#pragma unroll
    for (int i = 0; i < 4; i++) {
        int row = row0 + tr * 4 + i;
#pragma unroll
        for (int j = 0; j < 12; j++) {
            int n = tc * 12 + j;
            float v = acc[i][j];
            if (n < 64)       g_q[row * H_ + n]       = v;
            else if (n < 128) g_k[row * H_ + n - 64]  = v;
            else              g_v[row * H_ + n - 128] = v;
        }
    }
}

// ===========================================================================
// Kernel 2: causal flash attention, fp32.
// Grid: (32 q-tiles x 8 batches) flattened; block 256 threads = 8 warps.
// Each warp: 8 query rows x full 64-key tile; per-lane 4x4 micro-tile.
// Online softmax; P staged per-warp in smem for the PV pass.
// Dynamic smem layout (floats):
//   Qs[64][65]  Kt[64][68] (K transposed: [d][s])  Vs[64][68]  Ps[8][8][65]
// ===========================================================================
#define QS_STRIDE 65
#define KT_STRIDE 68
#define VS_STRIDE 68
#define PS_STRIDE 65
#define QS_OFF 0
#define KT_OFF (64 * QS_STRIDE)                 // 4160
#define VS_OFF (KT_OFF + 64 * KT_STRIDE)        // 8512
#define PS_OFF (VS_OFF + 64 * VS_STRIDE)        // 12864
#define SMEM_FLOATS (PS_OFF + 8 * 8 * PS_STRIDE) // 17024
#define ATTN_SMEM_BYTES (SMEM_FLOATS * 4)        // 68096

__global__ __launch_bounds__(256)
void attn_kernel(float* __restrict__ out)
{
    extern __shared__ float sm[];
    float* Qs = sm + QS_OFF;
    float* Kt = sm + KT_OFF;
    float* Vs = sm + VS_OFF;

    const int tid  = threadIdx.x;
    const int w    = tid >> 5;            // warp 0..7
    const int lane = tid & 31;
    const int rg   = lane >> 4;           // row group 0..1
    const int cg   = lane & 15;           // col group 0..15

    float* Ps = sm + PS_OFF + w * (8 * PS_STRIDE);

    // heavy q-tiles first for better tail behavior
    const int qt = 31 - (blockIdx.x >> 3);
    const int b  = blockIdx.x & 7;
    const int qrow0 = qt * 64;            // tile base (local to batch)
    const int gbase = b * T_;             // row offset of this batch

    // load Q tile once
    for (int idx = tid; idx < 64 * 64; idx += 256) {
        int r = idx >> 6, d = idx & 63;
        Qs[r * QS_STRIDE + d] = g_q[(gbase + qrow0 + r) * H_ + d];
    }

    const int rloc = w * 8 + rg * 4;      // this lane's first local row
    const int qbase = rloc * QS_STRIDE;

    float o[4][4];
    float m_run[4], l_run[4];
#pragma unroll
    for (int i = 0; i < 4; i++) {
        m_run[i] = -CUDART_INF_F;
        l_run[i] = 0.0f;
#pragma unroll
        for (int j = 0; j < 4; j++) o[i][j] = 0.0f;
    }

    const float scale = 0.125f;           // 1/sqrt(64)

    const int lc_d = tid & 63;            // loader: head dim
    const int lc_s0 = tid >> 6;           // loader: seq group (4)

    for (int kt = 0; kt <= qt; kt++) {
        __syncthreads();  // prev PV / Q-load complete before overwriting tiles

        // load K (transposed -> Kt[d][s]) and V (natural Vs[s][d])
        const int srow0 = gbase + kt * 64;
#pragma unroll
        for (int ii = 0; ii < 16; ii++) {
            int s = lc_s0 + ii * 4;
            float kv = g_k[(srow0 + s) * H_ + lc_d];
            Kt[lc_d * KT_STRIDE + s] = kv;
            Vs[s * VS_STRIDE + lc_d] = g_v[(srow0 + s) * H_ + lc_d];
        }
        __syncthreads();

        // ---- S = Q K^T (per-lane 4x4 over rows rloc..rloc+3, cols cg*4..+3)
        float s4[4][4];
#pragma unroll
        for (int i = 0; i < 4; i++)
#pragma unroll
            for (int j = 0; j < 4; j++) s4[i][j] = 0.0f;

#pragma unroll 4
        for (int k = 0; k < 64; k++) {
            float4 bk = *(const float4*)(Kt + k * KT_STRIDE + (cg << 2));
            float a0 = Qs[qbase + k];
            float a1 = Qs[qbase + QS_STRIDE + k];
            float a2 = Qs[qbase + 2 * QS_STRIDE + k];
            float a3 = Qs[qbase + 3 * QS_STRIDE + k];
            s4[0][0] += a0 * bk.x; s4[0][1] += a0 * bk.y; s4[0][2] += a0 * bk.z; s4[0][3] += a0 * bk.w;
            s4[1][0] += a1 * bk.x; s4[1][1] += a1 * bk.y; s4[1][2] += a1 * bk.z; s4[1][3] += a1 * bk.w;
            s4[2][0] += a2 * bk.x; s4[2][1] += a2 * bk.y; s4[2][2] += a2 * bk.z; s4[2][3] += a2 * bk.w;
            s4[3][0] += a3 * bk.x; s4[3][1] += a3 * bk.y; s4[3][2] += a3 * bk.z; s4[3][3] += a3 * bk.w;
        }

        const bool diag = (kt == qt);
        float p[4][4];
#pragma unroll
        for (int i = 0; i < 4; i++) {
            // scale + causal mask
#pragma unroll
            for (int j = 0; j < 4; j++) {
                float v = s4[i][j] * scale;
                if (diag && ((cg << 2) + j > rloc + i)) v = -CUDART_INF_F;
                s4[i][j] = v;
            }
            // row max across 4 local + 16 cg lanes
            float mt = fmaxf(fmaxf(s4[i][0], s4[i][1]), fmaxf(s4[i][2], s4[i][3]));
#pragma unroll
            for (int off = 8; off >= 1; off >>= 1)
                mt = fmaxf(mt, __shfl_xor_sync(0xffffffffu, mt, off));

            float m_new = fmaxf(m_run[i], mt);
            float alpha = __expf(m_run[i] - m_new);
            float ls = 0.0f;
#pragma unroll
            for (int j = 0; j < 4; j++) {
                p[i][j] = __expf(s4[i][j] - m_new);
                ls += p[i][j];
            }
#pragma unroll
            for (int off = 8; off >= 1; off >>= 1)
                ls += __shfl_xor_sync(0xffffffffu, ls, off);

            l_run[i] = l_run[i] * alpha + ls;
            m_run[i] = m_new;
#pragma unroll
            for (int j = 0; j < 4; j++) o[i][j] *= alpha;
        }

        // stage P for the PV pass
#pragma unroll
        for (int i = 0; i < 4; i++)
#pragma unroll
            for (int j = 0; j < 4; j++)
                Ps[(rg * 4 + i) * PS_STRIDE + (cg << 2) + j] = p[i][j];
        __syncwarp();

        // ---- O += P V
#pragma unroll 4
        for (int s = 0; s < 64; s++) {
            float4 vv = *(const float4*)(Vs + s * VS_STRIDE + (cg << 2));
            float p0 = Ps[(rg * 4 + 0) * PS_STRIDE + s];
            float p1 = Ps[(rg * 4 + 1) * PS_STRIDE + s];
            float p2 = Ps[(rg * 4 + 2) * PS_STRIDE + s];
            float p3 = Ps[(rg * 4 + 3) * PS_STRIDE + s];
            o[0][0] += p0 * vv.x; o[0][1] += p0 * vv.y; o[0][2] += p0 * vv.z; o[0][3] += p0 * vv.w;
            o[1][0] += p1 * vv.x; o[1][1] += p1 * vv.y; o[1][2] += p1 * vv.z; o[1][3] += p1 * vv.w;
            o[2][0] += p2 * vv.x; o[2][1] += p2 * vv.y; o[2][2] += p2 * vv.z; o[2][3] += p2 * vv.w;
            o[3][0] += p3 * vv.x; o[3][1] += p3 * vv.y; o[3][2] += p3 * vv.z; o[3][3] += p3 * vv.w;
        }
    }

    // normalize + write out (float4 per row)
#pragma unroll
    for (int i = 0; i < 4; i++) {
        float inv = 1.0f / l_run[i];
        float4 r;
        r.x = o[i][0] * inv; r.y = o[i][1] * inv;
        r.z = o[i][2] * inv; r.w = o[i][3] * inv;
        int grow = gbase + qrow0 + rloc + i;
        *(float4*)(out + grow * H_ + (cg << 2)) = r;
    }
}

// ===========================================================================
extern "C" void kernel_launch(void* const* d_in, const int* in_sizes, int n_in,
                              void* d_out, int out_size)
{
    const float* x  = (const float*)d_in[0];
    const float* Wq = (const float*)d_in[1];
    const float* Wk = (const float*)d_in[2];
    const float* Wv = (const float*)d_in[3];
    float* out = (float*)d_out;

    // opt-in to >48KB dynamic smem (idempotent; not a stream op, capture-safe)
    cudaFuncSetAttribute(attn_kernel,
                         cudaFuncAttributeMaxDynamicSharedMemorySize,
                         ATTN_SMEM_BYTES);

    qkv_proj_kernel<<<ROWS / K1_BM, 256>>>(x, Wq, Wk, Wv);
    attn_kernel<<<(T_ / 64) * B_, 256, ATTN_SMEM_BYTES>>>(out);
}